// round 9
// baseline (speedup 1.0000x reference)
#include <cuda_runtime.h>
#include <cuda_fp16.h>
#include <cstdint>

// CapsuleLayer: B=32, I=32, C=2048, U=64, O=32, 3 routing iterations.
//  k_gemm_mma : fp16 mma.sync m16n8k16. W via cp.async -> fp32 smem (swizzled),
//               frags = LDS.128 + cvt. Direct half2 u_hat stores. s1 fused.
//  k_squash   : reduce s partials -> squash -> v (fp32 out) + transposed fp16 vh.
//  k_fused    : per routing step one DRAM pass; prefetch next channel ACROSS the
//               cluster barrier; phase C re-reads current channel from L1.

__device__ __half g_uhat[134217728];  // 256 MB (c,b,u,o): c*65536 + b*2048 + uo
__device__ float g_sparts[16777216];  // 256 slots x 65536 (b*2048 + uo)
__device__ __half g_vh[65536];        // v, fp16, layout (u,op,[b*2+par]): (u*16+op)*64 + b*2 + (o&1)
__device__ float g_b[131072];         // routing logits (C,U)

__global__ void k_nop() {}

#define WSTAGE 32768                   // one W tile: 256 rows x 128B fp32
#define SM_TOT (2 * WSTAGE + 16384)    // + x_h 16KB

__device__ __forceinline__ void mma16816(float d[4], uint32_t a0, uint32_t a1,
                                         uint32_t a2, uint32_t a3,
                                         uint32_t b0, uint32_t b1) {
    asm volatile(
        "mma.sync.aligned.m16n8k16.row.col.f32.f16.f16.f32 "
        "{%0,%1,%2,%3}, {%4,%5,%6,%7}, {%8,%9}, {%0,%1,%2,%3};"
        : "+f"(d[0]), "+f"(d[1]), "+f"(d[2]), "+f"(d[3])
        : "r"(a0), "r"(a1), "r"(a2), "r"(a3), "r"(b0), "r"(b1));
}

__global__ __launch_bounds__(256, 2) void k_gemm_mma(const float* __restrict__ x,
                                                     const float* __restrict__ w) {
    extern __shared__ char smem[];
    float* wsm = reinterpret_cast<float*>(smem);           // 2 x 32KB, swizzled
    __half* x_h = reinterpret_cast<__half*>(smem + 2 * WSTAGE);
    const int tid = threadIdx.x;
    const int warp = tid >> 5, lane = tid & 31;
    const int r = lane >> 2, q = lane & 3;
    const int c0 = blockIdx.x * 8;

    // cp.async one W tile (tile n: channel c0+(n&7), p-rows (n>>3)*256..+255)
    auto issue = [&](int n) {
        const float* src = w + ((long)(c0 + (n & 7)) * 2048 + (long)(n >> 3) * 256) * 32;
        char* dst = smem + (n & 1) * WSTAGE;
#pragma unroll
        for (int it = 0; it < 8; it++) {
            int lin = it * 256 + tid;
            int row = lin >> 3, cq = lin & 7;
            int col = cq ^ ((row & 1) << 2);   // parity swizzle -> conflict-free LDS.128
            asm volatile("cp.async.cg.shared.global [%0], [%1], 16;"
                :: "r"((uint32_t)__cvta_generic_to_shared(dst + row * 128 + col * 16)),
                   "l"(src + row * 32 + cq * 4) : "memory");
        }
        asm volatile("cp.async.commit_group;" ::: "memory");
    };
    issue(0);

    // Stage x -> fp16 smem: x_h[cc][b][i]
    for (int idx = tid; idx < 8192; idx += 256) {
        int cc = idx & 7, bi = idx >> 3;
        x_h[cc * 1024 + bi] = __float2half_rn(x[bi * 2048 + c0 + cc]);
    }

    float sacc[4][2][4];

    for (int n = 0; n < 64; n++) {
        const int cc = n & 7, chunk = n >> 3;
        const int c = c0 + cc;

        asm volatile("cp.async.wait_group 0;" ::: "memory");
        __syncthreads();                 // tile n visible to all warps (also x_h at n=0)
        if (n < 63) issue(n + 1);        // overlaps with compute below

        if (cc == 0) {
#pragma unroll
            for (int nt = 0; nt < 4; nt++)
#pragma unroll
                for (int bt = 0; bt < 2; bt++)
#pragma unroll
                    for (int jj = 0; jj < 4; jj++) sacc[nt][bt][jj] = 0.f;
        }

        // A fragments (logical-k permutation; matches B below)
        uint32_t A[2][2][4];
#pragma unroll
        for (int bt = 0; bt < 2; bt++)
#pragma unroll
            for (int ks = 0; ks < 2; ks++) {
                uint2 v1 = *reinterpret_cast<const uint2*>(
                    &x_h[cc * 1024 + (bt * 16 + r) * 32 + ks * 16 + q * 4]);
                uint2 v2 = *reinterpret_cast<const uint2*>(
                    &x_h[cc * 1024 + (bt * 16 + r + 8) * 32 + ks * 16 + q * 4]);
                A[bt][ks][0] = v1.x;
                A[bt][ks][1] = v2.x;
                A[bt][ks][2] = v1.y;
                A[bt][ks][3] = v2.y;
            }

        float d[4][2][4];
#pragma unroll
        for (int nt = 0; nt < 4; nt++)
#pragma unroll
            for (int bt = 0; bt < 2; bt++)
#pragma unroll
                for (int jj = 0; jj < 4; jj++) d[nt][bt][jj] = 0.f;

        const float* wb = wsm + (n & 1) * 8192;
#pragma unroll
        for (int nt = 0; nt < 4; nt++) {
            const int p = warp * 32 + nt * 8 + r;
#pragma unroll
            for (int ks = 0; ks < 2; ks++) {
                int col = (ks * 4 + q) ^ ((p & 1) << 2);
                float4 bf = *reinterpret_cast<const float4*>(wb + p * 32 + col * 4);
                __half2 h0 = __floats2half2_rn(bf.x, bf.y);
                __half2 h1 = __floats2half2_rn(bf.z, bf.w);
                uint32_t b0 = *reinterpret_cast<uint32_t*>(&h0);
                uint32_t b1 = *reinterpret_cast<uint32_t*>(&h1);
                mma16816(d[nt][0], A[0][ks][0], A[0][ks][1], A[0][ks][2], A[0][ks][3], b0, b1);
                mma16816(d[nt][1], A[1][ks][0], A[1][ks][1], A[1][ks][2], A[1][ks][3], b0, b1);
            }
        }

        // Epilogue: s1 accumulate + DIRECT half2 stores (sector-aligned)
#pragma unroll
        for (int nt = 0; nt < 4; nt++)
#pragma unroll
            for (int bt = 0; bt < 2; bt++) {
#pragma unroll
                for (int jj = 0; jj < 4; jj++) sacc[nt][bt][jj] += d[nt][bt][jj];
                __half2 lo = __floats2half2_rn(d[nt][bt][0], d[nt][bt][1]);
                __half2 hi = __floats2half2_rn(d[nt][bt][2], d[nt][bt][3]);
                __half* base =
                    g_uhat + (long)c * 65536 + chunk * 256 + warp * 32 + nt * 8 + 2 * q;
                *reinterpret_cast<__half2*>(base + (bt * 16 + r) * 2048) = lo;
                *reinterpret_cast<__half2*>(base + (bt * 16 + r + 8) * 2048) = hi;
            }

        if (cc == 7) {   // s1 partials (c1 = 1/64)
            float* sp = g_sparts + blockIdx.x * 65536 + chunk * 256;
#pragma unroll
            for (int nt = 0; nt < 4; nt++)
#pragma unroll
                for (int bt = 0; bt < 2; bt++) {
                    int col = warp * 32 + nt * 8 + 2 * q;
                    int row = bt * 16 + r;
                    *reinterpret_cast<float2*>(sp + row * 2048 + col) =
                        make_float2(sacc[nt][bt][0] * 0.015625f, sacc[nt][bt][1] * 0.015625f);
                    *reinterpret_cast<float2*>(sp + (row + 8) * 2048 + col) =
                        make_float2(sacc[nt][bt][2] * 0.015625f, sacc[nt][bt][3] * 0.015625f);
                }
        }
    }
}

// ---------------------------------------------------------------------------
// Reduce s partials + squash; writes fp32 (g_v-equiv / output) and fp16 vh.
// ---------------------------------------------------------------------------
__global__ void k_squash(int nparts, float* __restrict__ out_ext, int use_ext) {
    int e = blockIdx.x * 256 + threadIdx.x;
    float a0 = 0.f, a1 = 0.f, a2 = 0.f, a3 = 0.f;
    int p = 0;
    for (; p + 3 < nparts; p += 4) {
        a0 += g_sparts[(p + 0) * 65536 + e];
        a1 += g_sparts[(p + 1) * 65536 + e];
        a2 += g_sparts[(p + 2) * 65536 + e];
        a3 += g_sparts[(p + 3) * 65536 + e];
    }
    for (; p < nparts; p++) a0 += g_sparts[p * 65536 + e];
    float s = (a0 + a1) + (a2 + a3);
    float sq = s * s;
#pragma unroll
    for (int off = 16; off > 0; off >>= 1)
        sq += __shfl_xor_sync(0xffffffffu, sq, off);
    float scale = sq / ((1.f + sq) * sqrtf(sq + 1e-8f));
    float res = s * scale;
    if (use_ext) out_ext[e] = res;
    // transposed fp16 copy for k_fused: (u*16+op)*64 + b*2 + (o&1)
    int o = e & 31, u = (e >> 5) & 63, b = e >> 11;
    g_vh[(u * 16 + (o >> 1)) * 64 + b * 2 + (o & 1)] = __float2half_rn(res);
}

// ---------------------------------------------------------------------------
// Fused routing step. grid 148 (74 clusters of 2), 512 thr, ~1KB smem.
// cur = prefetch buffer only: c+1 LDGs issued BEFORE the cluster barrier;
// phase C re-reads channel c from L1 (slice 64KB << L1).
// ---------------------------------------------------------------------------
__global__ __launch_bounds__(512, 1) __cluster_dims__(2, 1, 1)
void k_fused(int add_prior, int store_b) {
    __shared__ float agree_sm[256];    // [2 parity][2 rank][64 u]
    const int tid = threadIdx.x;
    const int w = tid >> 5, lane = tid & 31;
    const int us = lane >> 4, op = lane & 15;
    const int r = blockIdx.x & 1, peer = r ^ 1;
    const int cid = blockIdx.x >> 1, nclus = gridDim.x >> 1;
    const int c_start = (cid * 2048) / nclus;
    const int c_end = ((cid + 1) * 2048) / nclus;
    const int u0 = w * 2 + us;
    const long coff = (long)(r * 16) * 2048 + u0 * 32 + 2 * op;   // + j*1024 + bb*2048

    float2 sacc[2][16];
#pragma unroll
    for (int j = 0; j < 2; j++)
#pragma unroll
        for (int bb = 0; bb < 16; bb++) sacc[j][bb] = make_float2(0.f, 0.f);

    __half2 cur[2][16];
    {
        const __half* p = g_uhat + (long)c_start * 65536 + coff;
#pragma unroll
        for (int j = 0; j < 2; j++)
#pragma unroll
            for (int bb = 0; bb < 16; bb++)
                cur[j][bb] = __ldg(reinterpret_cast<const __half2*>(p + j * 1024 + bb * 2048));
    }

    for (int c = c_start; c < c_end; c++) {
        const int par = c & 1;

        // Phase A: agree from cur + vh (L1-resident after first channel)
        float agg[2];
#pragma unroll
        for (int j = 0; j < 2; j++) {
            const uint4* pv4 = reinterpret_cast<const uint4*>(
                g_vh + ((j * 32 + u0) * 16 + op) * 64 + r * 32);
            float a = 0.f;
#pragma unroll
            for (int qv = 0; qv < 4; qv++) {
                uint4 vq = __ldg(pv4 + qv);
                const uint32_t vs[4] = {vq.x, vq.y, vq.z, vq.w};
#pragma unroll
                for (int e2 = 0; e2 < 4; e2++) {
                    float2 f = __half22float2(cur[j][qv * 4 + e2]);
                    float2 vf = __half22float2(*reinterpret_cast<const __half2*>(&vs[e2]));
                    a += f.x * vf.x + f.y * vf.y;
                }
            }
            agg[j] = a;
        }
#pragma unroll
        for (int j = 0; j < 2; j++)
#pragma unroll
            for (int off = 8; off > 0; off >>= 1)
                agg[j] += __shfl_xor_sync(0xffffffffu, agg[j], off);

        if (op == 0) {
#pragma unroll
            for (int j = 0; j < 2; j++) {
                int u = j * 32 + u0;
                agree_sm[(par * 2 + r) * 64 + u] = agg[j];
                unsigned int la = (unsigned int)__cvta_generic_to_shared(
                    &agree_sm[(par * 2 + r) * 64 + u]);
                asm volatile(
                    "{.reg .b32 ra; mapa.shared::cluster.u32 ra, %0, %1;"
                    " st.shared::cluster.f32 [ra], %2;}"
                    :: "r"(la), "r"(peer), "f"(agg[j]));
            }
        }

        // Prefetch channel c+1 BEFORE the barrier (overlaps barrier + DRAM latency)
        if (c + 1 < c_end) {
            const __half* p = g_uhat + (long)(c + 1) * 65536 + coff;
#pragma unroll
            for (int j = 0; j < 2; j++)
#pragma unroll
                for (int bb = 0; bb < 16; bb++)
                    cur[j][bb] =
                        __ldg(reinterpret_cast<const __half2*>(p + j * 1024 + bb * 2048));
        }

        asm volatile("barrier.cluster.arrive.aligned;" ::: "memory");
        asm volatile("barrier.cluster.wait.aligned;" ::: "memory");

        // Merge halves, logits, softmax over 64 u (redundant per warp)
        float a0 = (agree_sm[(par * 2) * 64 + lane] +
                    agree_sm[(par * 2 + 1) * 64 + lane]) * 0.03125f;
        float a1 = (agree_sm[(par * 2) * 64 + 32 + lane] +
                    agree_sm[(par * 2 + 1) * 64 + 32 + lane]) * 0.03125f;
        if (add_prior) {
            a0 += g_b[c * 64 + lane];
            a1 += g_b[c * 64 + 32 + lane];
        }
        if (store_b && r == 0 && w == 0) {
            g_b[c * 64 + lane] = a0;
            g_b[c * 64 + 32 + lane] = a1;
        }
        float m = fmaxf(a0, a1);
#pragma unroll
        for (int off = 16; off > 0; off >>= 1)
            m = fmaxf(m, __shfl_xor_sync(0xffffffffu, m, off));
        float e0 = expf(a0 - m), e1 = expf(a1 - m);
        float sume = e0 + e1;
#pragma unroll
        for (int off = 16; off > 0; off >>= 1)
            sume += __shfl_xor_sync(0xffffffffu, sume, off);
        float inv = 1.f / sume;
        float c0v = e0 * inv, c1v = e1 * inv;
        float cn[2];
        cn[0] = __shfl_sync(0xffffffffu, c0v, u0);
        cn[1] = __shfl_sync(0xffffffffu, c1v, u0);

        // Phase C: re-read channel c (L1 hit), accumulate s
#pragma unroll
        for (int j = 0; j < 2; j++) {
            const __half* pc = g_uhat + (long)c * 65536 + coff + j * 1024;
            const float cj = cn[j];
#pragma unroll
            for (int bb = 0; bb < 16; bb++) {
                float2 f = __half22float2(
                    __ldg(reinterpret_cast<const __half2*>(pc + bb * 2048)));
                sacc[j][bb].x += cj * f.x;
                sacc[j][bb].y += cj * f.y;
            }
        }
    }

    float* sp = g_sparts + cid * 65536 + coff;
#pragma unroll
    for (int j = 0; j < 2; j++)
#pragma unroll
        for (int bb = 0; bb < 16; bb++)
            *reinterpret_cast<float2*>(sp + j * 1024 + bb * 2048) = sacc[j][bb];
}

// ---------------------------------------------------------------------------

extern "C" void kernel_launch(void* const* d_in, const int* in_sizes, int n_in,
                              void* d_out, int out_size) {
    const float* x = (const float*)d_in[0];
    const float* w = (const float*)d_in[1];
    if (in_sizes[0] > in_sizes[1]) { const float* t = x; x = w; w = t; }
    float* out = (float*)d_out;

    cudaFuncSetAttribute(k_gemm_mma, cudaFuncAttributeMaxDynamicSharedMemorySize, SM_TOT);

    k_nop<<<1, 32>>>();                        // #1 (profiler alignment: -s 5 -> #6)
    k_gemm_mma<<<256, 256, SM_TOT>>>(x, w);    // #2: u_hat(fp16) + s1 partials
    k_squash<<<256, 256>>>(256, out, 0);       // #3: v1 (+ vh)
    k_fused<<<148, 512>>>(0, 1);               // #4: agree1 -> b2 -> c2 -> s2
    k_squash<<<256, 256>>>(74, out, 0);        // #5: v2 (+ vh)
    k_fused<<<148, 512>>>(1, 0);               // #6: agree2 -> b3 -> c3 -> s3 (ncu)
    k_squash<<<256, 256>>>(74, out, 1);        // #7: v3 -> output
}

// round 10
// speedup vs baseline: 1.3419x; 1.3419x over previous
#include <cuda_runtime.h>
#include <cuda_fp16.h>
#include <cstdint>

// CapsuleLayer: B=32, I=32, C=2048, U=64, O=32, 3 routing iterations.
//  k_gemm_mma : fp16 mma.sync m16n8k16; W via cp.async->fp32 smem (swizzled),
//               frags = LDS.128 + cvt; direct half2 u_hat stores; s1 fused. (R9)
//  k_squash   : reduce s partials -> squash -> v (fp32 out) + fp16 copy g_vh.
//  k_fused    : per routing step one DRAM pass. Channel slices staged via
//               cp.async double-buffer in smem; phases A and C read smem (LDS);
//               next channel's DMA overlaps the cluster-barrier/softmax chain.

__device__ __half g_uhat[134217728];  // 256 MB (c,b,u,o): c*65536 + b*2048 + uo
__device__ float g_sparts[16777216];  // 256 slots x 65536 (b*2048 + uo)
__device__ __half g_vh[65536];        // v fp16, layout (b,u,o) = b*2048 + u*32 + o
__device__ float g_b[131072];         // routing logits (C,U)

__global__ void k_nop() {}

// ---------------- gemm (unchanged from R9) ----------------
#define WSTAGE 32768
#define SM_TOT (2 * WSTAGE + 16384)

__device__ __forceinline__ void mma16816(float d[4], uint32_t a0, uint32_t a1,
                                         uint32_t a2, uint32_t a3,
                                         uint32_t b0, uint32_t b1) {
    asm volatile(
        "mma.sync.aligned.m16n8k16.row.col.f32.f16.f16.f32 "
        "{%0,%1,%2,%3}, {%4,%5,%6,%7}, {%8,%9}, {%0,%1,%2,%3};"
        : "+f"(d[0]), "+f"(d[1]), "+f"(d[2]), "+f"(d[3])
        : "r"(a0), "r"(a1), "r"(a2), "r"(a3), "r"(b0), "r"(b1));
}

__global__ __launch_bounds__(256, 2) void k_gemm_mma(const float* __restrict__ x,
                                                     const float* __restrict__ w) {
    extern __shared__ char smem[];
    float* wsm = reinterpret_cast<float*>(smem);
    __half* x_h = reinterpret_cast<__half*>(smem + 2 * WSTAGE);
    const int tid = threadIdx.x;
    const int warp = tid >> 5, lane = tid & 31;
    const int r = lane >> 2, q = lane & 3;
    const int c0 = blockIdx.x * 8;

    auto issue = [&](int n) {
        const float* src = w + ((long)(c0 + (n & 7)) * 2048 + (long)(n >> 3) * 256) * 32;
        char* dst = smem + (n & 1) * WSTAGE;
#pragma unroll
        for (int it = 0; it < 8; it++) {
            int lin = it * 256 + tid;
            int row = lin >> 3, cq = lin & 7;
            int col = cq ^ ((row & 1) << 2);
            asm volatile("cp.async.cg.shared.global [%0], [%1], 16;"
                :: "r"((uint32_t)__cvta_generic_to_shared(dst + row * 128 + col * 16)),
                   "l"(src + row * 32 + cq * 4) : "memory");
        }
        asm volatile("cp.async.commit_group;" ::: "memory");
    };
    issue(0);

    for (int idx = tid; idx < 8192; idx += 256) {
        int cc = idx & 7, bi = idx >> 3;
        x_h[cc * 1024 + bi] = __float2half_rn(x[bi * 2048 + c0 + cc]);
    }

    float sacc[4][2][4];

    for (int n = 0; n < 64; n++) {
        const int cc = n & 7, chunk = n >> 3;
        const int c = c0 + cc;

        asm volatile("cp.async.wait_group 0;" ::: "memory");
        __syncthreads();
        if (n < 63) issue(n + 1);

        if (cc == 0) {
#pragma unroll
            for (int nt = 0; nt < 4; nt++)
#pragma unroll
                for (int bt = 0; bt < 2; bt++)
#pragma unroll
                    for (int jj = 0; jj < 4; jj++) sacc[nt][bt][jj] = 0.f;
        }

        uint32_t A[2][2][4];
#pragma unroll
        for (int bt = 0; bt < 2; bt++)
#pragma unroll
            for (int ks = 0; ks < 2; ks++) {
                uint2 v1 = *reinterpret_cast<const uint2*>(
                    &x_h[cc * 1024 + (bt * 16 + r) * 32 + ks * 16 + q * 4]);
                uint2 v2 = *reinterpret_cast<const uint2*>(
                    &x_h[cc * 1024 + (bt * 16 + r + 8) * 32 + ks * 16 + q * 4]);
                A[bt][ks][0] = v1.x;
                A[bt][ks][1] = v2.x;
                A[bt][ks][2] = v1.y;
                A[bt][ks][3] = v2.y;
            }

        float d[4][2][4];
#pragma unroll
        for (int nt = 0; nt < 4; nt++)
#pragma unroll
            for (int bt = 0; bt < 2; bt++)
#pragma unroll
                for (int jj = 0; jj < 4; jj++) d[nt][bt][jj] = 0.f;

        const float* wb = wsm + (n & 1) * 8192;
#pragma unroll
        for (int nt = 0; nt < 4; nt++) {
            const int p = warp * 32 + nt * 8 + r;
#pragma unroll
            for (int ks = 0; ks < 2; ks++) {
                int col = (ks * 4 + q) ^ ((p & 1) << 2);
                float4 bf = *reinterpret_cast<const float4*>(wb + p * 32 + col * 4);
                __half2 h0 = __floats2half2_rn(bf.x, bf.y);
                __half2 h1 = __floats2half2_rn(bf.z, bf.w);
                uint32_t b0 = *reinterpret_cast<uint32_t*>(&h0);
                uint32_t b1 = *reinterpret_cast<uint32_t*>(&h1);
                mma16816(d[nt][0], A[0][ks][0], A[0][ks][1], A[0][ks][2], A[0][ks][3], b0, b1);
                mma16816(d[nt][1], A[1][ks][0], A[1][ks][1], A[1][ks][2], A[1][ks][3], b0, b1);
            }
        }

#pragma unroll
        for (int nt = 0; nt < 4; nt++)
#pragma unroll
            for (int bt = 0; bt < 2; bt++) {
#pragma unroll
                for (int jj = 0; jj < 4; jj++) sacc[nt][bt][jj] += d[nt][bt][jj];
                __half2 lo = __floats2half2_rn(d[nt][bt][0], d[nt][bt][1]);
                __half2 hi = __floats2half2_rn(d[nt][bt][2], d[nt][bt][3]);
                __half* base =
                    g_uhat + (long)c * 65536 + chunk * 256 + warp * 32 + nt * 8 + 2 * q;
                *reinterpret_cast<__half2*>(base + (bt * 16 + r) * 2048) = lo;
                *reinterpret_cast<__half2*>(base + (bt * 16 + r + 8) * 2048) = hi;
            }

        if (cc == 7) {
            float* sp = g_sparts + blockIdx.x * 65536 + chunk * 256;
#pragma unroll
            for (int nt = 0; nt < 4; nt++)
#pragma unroll
                for (int bt = 0; bt < 2; bt++) {
                    int col = warp * 32 + nt * 8 + 2 * q;
                    int row = bt * 16 + r;
                    *reinterpret_cast<float2*>(sp + row * 2048 + col) =
                        make_float2(sacc[nt][bt][0] * 0.015625f, sacc[nt][bt][1] * 0.015625f);
                    *reinterpret_cast<float2*>(sp + (row + 8) * 2048 + col) =
                        make_float2(sacc[nt][bt][2] * 0.015625f, sacc[nt][bt][3] * 0.015625f);
                }
        }
    }
}

// ---------------- squash ----------------
__global__ void k_squash(int nparts, float* __restrict__ out_ext, int use_ext) {
    int e = blockIdx.x * 256 + threadIdx.x;
    float a0 = 0.f, a1 = 0.f, a2 = 0.f, a3 = 0.f;
    int p = 0;
    for (; p + 3 < nparts; p += 4) {
        a0 += g_sparts[(p + 0) * 65536 + e];
        a1 += g_sparts[(p + 1) * 65536 + e];
        a2 += g_sparts[(p + 2) * 65536 + e];
        a3 += g_sparts[(p + 3) * 65536 + e];
    }
    for (; p < nparts; p++) a0 += g_sparts[p * 65536 + e];
    float s = (a0 + a1) + (a2 + a3);
    float sq = s * s;
#pragma unroll
    for (int off = 16; off > 0; off >>= 1)
        sq += __shfl_xor_sync(0xffffffffu, sq, off);
    float scale = sq / ((1.f + sq) * sqrtf(sq + 1e-8f));
    float res = s * scale;
    if (use_ext) out_ext[e] = res;
    g_vh[e] = __float2half_rn(res);
}

// ---------------- fused routing step ----------------
// smem: vh 64KB | stage[2] 2x64KB | agree 1KB  (193KB, 1 CTA/SM)
#define FS_VH 0
#define FS_STAGE 65536
#define FS_AGREE 196608
#define FS_TOT 197632

__global__ __launch_bounds__(512, 1) __cluster_dims__(2, 1, 1)
void k_fused(int add_prior, int store_b) {
    extern __shared__ char fsm[];
    __half* vh_sm = reinterpret_cast<__half*>(fsm + FS_VH);
    float* agree_sm = reinterpret_cast<float*>(fsm + FS_AGREE);

    const int tid = threadIdx.x;
    const int w = tid >> 5, lane = tid & 31;
    const int us = lane >> 4, op = lane & 15;
    const int r = blockIdx.x & 1, peer = r ^ 1;
    const int cid = blockIdx.x >> 1, nclus = gridDim.x >> 1;
    const int c_start = (cid * 2048) / nclus;
    const int c_end = ((cid + 1) * 2048) / nclus;
    const int u0 = w * 2 + us;
    const int toff = u0 * 32 + 2 * op;   // within slice: + j*1024 + bb*2048

    // Load this CTA's b-half of v (fp16), coalesced
    {
        const uint4* src = reinterpret_cast<const uint4*>(g_vh + r * 32768);
        uint4* dst = reinterpret_cast<uint4*>(vh_sm);
        for (int idx = tid; idx < 4096; idx += 512) dst[idx] = src[idx];
    }

    // DMA one channel slice (64KB) into stage buffer
    auto stage_issue = [&](int c, int buf) {
        const char* src = reinterpret_cast<const char*>(
            g_uhat + (long)c * 65536 + (long)r * 32768);
        uint32_t dst = (uint32_t)__cvta_generic_to_shared(fsm + FS_STAGE + buf * 65536);
#pragma unroll
        for (int it = 0; it < 8; it++) {
            int off = (it * 512 + tid) * 16;
            asm volatile("cp.async.cg.shared.global [%0], [%1], 16;"
                         :: "r"(dst + off), "l"(src + off) : "memory");
        }
        asm volatile("cp.async.commit_group;" ::: "memory");
    };
    stage_issue(c_start, 0);
    if (c_start + 1 < c_end) stage_issue(c_start + 1, 1);
    else asm volatile("cp.async.commit_group;" ::: "memory");

    float2 sacc[2][16];
#pragma unroll
    for (int j = 0; j < 2; j++)
#pragma unroll
        for (int bb = 0; bb < 16; bb++) sacc[j][bb] = make_float2(0.f, 0.f);

    __syncthreads();   // vh_sm ready

    for (int c = c_start; c < c_end; c++) {
        const int m = c - c_start;
        const int buf = m & 1;
        const int par = c & 1;
        const __half* st = reinterpret_cast<const __half*>(fsm + FS_STAGE + buf * 65536);

        asm volatile("cp.async.wait_group 1;" ::: "memory");
        __syncthreads();   // stage[buf] visible to all warps

        // Phase A: agree from smem stage + smem v
        float agg[2];
#pragma unroll
        for (int j = 0; j < 2; j++) {
            const __half* pu = st + j * 1024 + toff;
            const __half* pv = vh_sm + j * 1024 + toff;
            float a = 0.f;
#pragma unroll
            for (int bb = 0; bb < 16; bb++) {
                float2 f = __half22float2(
                    *reinterpret_cast<const __half2*>(pu + bb * 2048));
                float2 vf = __half22float2(
                    *reinterpret_cast<const __half2*>(pv + bb * 2048));
                a += f.x * vf.x + f.y * vf.y;
            }
            agg[j] = a;
        }
#pragma unroll
        for (int j = 0; j < 2; j++)
#pragma unroll
            for (int off = 8; off > 0; off >>= 1)
                agg[j] += __shfl_xor_sync(0xffffffffu, agg[j], off);

        if (op == 0) {
#pragma unroll
            for (int j = 0; j < 2; j++) {
                int u = j * 32 + u0;
                agree_sm[(par * 2 + r) * 64 + u] = agg[j];
                unsigned int la = (unsigned int)__cvta_generic_to_shared(
                    &agree_sm[(par * 2 + r) * 64 + u]);
                asm volatile(
                    "{.reg .b32 ra; mapa.shared::cluster.u32 ra, %0, %1;"
                    " st.shared::cluster.f32 [ra], %2;}"
                    :: "r"(la), "r"(peer), "f"(agg[j]));
            }
        }
        asm volatile("barrier.cluster.arrive.aligned;" ::: "memory");
        asm volatile("barrier.cluster.wait.aligned;" ::: "memory");

        // Merge halves, logits, softmax over 64 u (redundant per warp)
        float a0 = (agree_sm[(par * 2) * 64 + lane] +
                    agree_sm[(par * 2 + 1) * 64 + lane]) * 0.03125f;
        float a1 = (agree_sm[(par * 2) * 64 + 32 + lane] +
                    agree_sm[(par * 2 + 1) * 64 + 32 + lane]) * 0.03125f;
        if (add_prior) {
            a0 += g_b[c * 64 + lane];
            a1 += g_b[c * 64 + 32 + lane];
        }
        if (store_b && r == 0 && w == 0) {
            g_b[c * 64 + lane] = a0;
            g_b[c * 64 + 32 + lane] = a1;
        }
        float mx = fmaxf(a0, a1);
#pragma unroll
        for (int off = 16; off > 0; off >>= 1)
            mx = fmaxf(mx, __shfl_xor_sync(0xffffffffu, mx, off));
        float e0 = expf(a0 - mx), e1 = expf(a1 - mx);
        float sume = e0 + e1;
#pragma unroll
        for (int off = 16; off > 0; off >>= 1)
            sume += __shfl_xor_sync(0xffffffffu, sume, off);
        float inv = 1.f / sume;
        float c0v = e0 * inv, c1v = e1 * inv;
        float cn[2];
        cn[0] = __shfl_sync(0xffffffffu, c0v, u0);
        cn[1] = __shfl_sync(0xffffffffu, c1v, u0);

        // Phase C: s accumulation from smem stage
#pragma unroll
        for (int j = 0; j < 2; j++) {
            const __half* pu = st + j * 1024 + toff;
            const float cj = cn[j];
#pragma unroll
            for (int bb = 0; bb < 16; bb++) {
                float2 f = __half22float2(
                    *reinterpret_cast<const __half2*>(pu + bb * 2048));
                sacc[j][bb].x += cj * f.x;
                sacc[j][bb].y += cj * f.y;
            }
        }

        // Reuse buf for channel c+2 (all warps done reading stage[buf])
        __syncthreads();
        if (c + 2 < c_end) stage_issue(c + 2, buf);
        else asm volatile("cp.async.commit_group;" ::: "memory");
    }

    float* sp = g_sparts + cid * 65536 + (long)(r * 16) * 2048 + toff;
#pragma unroll
    for (int j = 0; j < 2; j++)
#pragma unroll
        for (int bb = 0; bb < 16; bb++)
            *reinterpret_cast<float2*>(sp + j * 1024 + bb * 2048) = sacc[j][bb];
}

// ---------------------------------------------------------------------------

extern "C" void kernel_launch(void* const* d_in, const int* in_sizes, int n_in,
                              void* d_out, int out_size) {
    const float* x = (const float*)d_in[0];
    const float* w = (const float*)d_in[1];
    if (in_sizes[0] > in_sizes[1]) { const float* t = x; x = w; w = t; }
    float* out = (float*)d_out;

    cudaFuncSetAttribute(k_gemm_mma, cudaFuncAttributeMaxDynamicSharedMemorySize, SM_TOT);
    cudaFuncSetAttribute(k_fused, cudaFuncAttributeMaxDynamicSharedMemorySize, FS_TOT);

    k_nop<<<1, 32>>>();                         // #1 (ncu -s 5 -> #6)
    k_gemm_mma<<<256, 256, SM_TOT>>>(x, w);     // #2: u_hat(fp16) + s1 partials
    k_squash<<<256, 256>>>(256, out, 0);        // #3: v1 (+ fp16 copy)
    k_fused<<<148, 512, FS_TOT>>>(0, 1);        // #4: agree1 -> b2 -> c2 -> s2
    k_squash<<<256, 256>>>(74, out, 0);         // #5: v2
    k_fused<<<148, 512, FS_TOT>>>(1, 0);        // #6: agree2 -> b3 -> c3 -> s3 (ncu)
    k_squash<<<256, 256>>>(74, out, 1);         // #7: v3 -> output
}